// round 14
// baseline (speedup 1.0000x reference)
#include <cuda_runtime.h>
#include <cuda_fp16.h>
#include <cuda_bf16.h>
#include <math.h>
#include <stdint.h>

#define NN 50000
#define NE 600000
#define NFEAT 256
#define NHID 128
#define NCLASS 40
#define RS 40  // padded smem row stride in fp16 elems (80B) -> conflict-free ldmatrix

// ---------------- scratch (no allocations allowed) ----------------
__device__ __half g_sup[(size_t)NN * NHID];    // support (h @ W) in fp16
__device__ __half g_sup3[(size_t)NN * NCLASS];
__device__ __half g_hh[(size_t)NN * NHID];
__device__ __half g_w1[128 * 256];
__device__ __half g_w2[128 * 128];
__device__ __half g_w3[64 * 128];
__device__ int  g_cnt[NN];
__device__ int  g_off[NN + 1];
__device__ int  g_cur[NN];
__device__ int2 g_edge[NE];

// ---------------- helpers ----------------
__device__ __forceinline__ uint32_t smem_u32(const void* p) {
    uint32_t a;
    asm("{ .reg .u64 t; cvta.to.shared.u64 t, %1; cvt.u32.u64 %0, t; }" : "=r"(a) : "l"(p));
    return a;
}
#define LDSM4(r, addr) \
    asm volatile("ldmatrix.sync.aligned.m8n8.x4.shared.b16 {%0,%1,%2,%3}, [%4];" \
        : "=r"((r)[0]), "=r"((r)[1]), "=r"((r)[2]), "=r"((r)[3]) : "r"(addr))
#define MMA_FP16(c, a, b) \
    asm volatile("mma.sync.aligned.m16n8k16.row.col.f32.f16.f16.f32 " \
        "{%0,%1,%2,%3}, {%4,%5,%6,%7}, {%8,%9}, {%0,%1,%2,%3};" \
        : "+f"((c)[0]), "+f"((c)[1]), "+f"((c)[2]), "+f"((c)[3]) \
        : "r"((a)[0]), "r"((a)[1]), "r"((a)[2]), "r"((a)[3]), "r"((b)[0]), "r"((b)[1]))
#define CP_ASYNC16(dst, src, sz) \
    asm volatile("cp.async.cg.shared.global [%0], [%1], 16, %2;" \
        :: "r"(dst), "l"(src), "r"(sz))
#define CP_COMMIT() asm volatile("cp.async.commit_group;")
#define CP_WAIT1()  asm volatile("cp.async.wait_group 1;")
#define CP_WAIT0()  asm volatile("cp.async.wait_group 0;")

// ---------------- weight transpose -> fp16, [N][K] ----------------
__global__ void prep_weights(const float* __restrict__ W1, const float* __restrict__ W2,
                             const float* __restrict__ W3) {
    int i = blockIdx.x * blockDim.x + threadIdx.x;
    const int S1 = 128 * 256, S2 = 128 * 128, S3 = 64 * 128;
    float v; __half* dst; int o;
    if (i < S1) {
        int n = i / 256, k = i % 256;
        v = W1[k * 128 + n]; o = i; dst = g_w1;
    } else if (i < S1 + S2) {
        int j = i - S1; int n = j / 128, k = j % 128;
        v = W2[k * 128 + n]; o = j; dst = g_w2;
    } else if (i < S1 + S2 + S3) {
        int j = i - S1 - S2; int n = j / 128, k = j % 128;
        v = (n < NCLASS) ? W3[k * NCLASS + n] : 0.f; o = j; dst = g_w3;
    } else return;
    dst[o] = __float2half(v);
}

// ---------------- CSR build (2 edges/thread) ----------------
__global__ void count_kernel(const int* __restrict__ dst, int* __restrict__ cnt) {
    int i = blockIdx.x * blockDim.x + threadIdx.x;
    if (2 * i >= NE) return;
    int2 d = *(const int2*)&dst[2 * i];
    atomicAdd(&cnt[d.x], 1);
    atomicAdd(&cnt[d.y], 1);
}
__global__ void scan_kernel(const int* __restrict__ cnt, int* __restrict__ off,
                            int* __restrict__ cur) {
    __shared__ int ssum[1024];
    const int t = threadIdx.x;
    const int CH = (NN + 1023) / 1024;
    const int start = t * CH;
    int s = 0;
    for (int j = 0; j < CH; j++) { int i = start + j; if (i < NN) s += cnt[i]; }
    ssum[t] = s;
    __syncthreads();
    for (int d = 1; d < 1024; d <<= 1) {
        int v = (t >= d) ? ssum[t - d] : 0;
        __syncthreads();
        ssum[t] += v;
        __syncthreads();
    }
    int run = (t > 0) ? ssum[t - 1] : 0;
    for (int j = 0; j < CH; j++) {
        int i = start + j;
        if (i < NN) { off[i] = run; cur[i] = run; run += cnt[i]; }
    }
    if (t == 1023) off[NN] = ssum[1023];
}
__global__ void scatter_kernel(const int* __restrict__ dst, const int* __restrict__ src,
                               const float* __restrict__ w, int* __restrict__ cur,
                               int2* __restrict__ edge) {
    int i = blockIdx.x * blockDim.x + threadIdx.x;
    if (2 * i >= NE) return;
    int2 d = *(const int2*)&dst[2 * i];
    int2 s = *(const int2*)&src[2 * i];
    float2 ww = *(const float2*)&w[2 * i];
    int p0 = atomicAdd(&cur[d.x], 1);
    edge[p0] = make_int2(s.x, __float_as_int(ww.x));
    int p1 = atomicAdd(&cur[d.y], 1);
    edge[p1] = make_int2(s.y, __float_as_int(ww.y));
}

// ---------------- GEMM1: A fp32 (x) converted in-kernel, B fp16; C fp16 ----------------
__global__ void __launch_bounds__(256, 1)
gemm1_mma(const float* __restrict__ A, const __half* __restrict__ B,
          __half* __restrict__ Cmat, int M) {
    extern __shared__ char smem[];
    constexpr int KTOT = 256, NT = 128, NCH = 8;
    constexpr int NP  = NT / 32;
    constexpr int NT8 = NT / 16;
    constexpr int A_BYTES = 128 * RS * 2;  // fp16 tile after convert
    constexpr int B_BYTES = NT * RS * 2;
    constexpr int STAGE = A_BYTES + B_BYTES;

    const uint32_t sb = smem_u32(smem);
    const int tid = threadIdx.x, wid = tid >> 5, lane = tid & 31;
    const int warpM = wid & 3, warpN = wid >> 2;
    const int m0 = warpM * 32, n0 = warpN * (NT / 2);
    const int row0 = blockIdx.x * 128;

    float acc[2][NT8][4];
#pragma unroll
    for (int a = 0; a < 2; a++)
#pragma unroll
        for (int b = 0; b < NT8; b++)
#pragma unroll
            for (int c = 0; c < 4; c++) acc[a][b][c] = 0.f;

    float4 ar[4];
    auto load_A_regs = [&](int kt) {
#pragma unroll
        for (int i = 0; i < 4; i++) {
            int idx = tid + i * 256;
            int r = idx >> 3, c4 = idx & 7;
            int gr = row0 + r;
            ar[i] = (gr < M) ? *(const float4*)&A[(size_t)gr * KTOT + kt * 32 + c4 * 4]
                             : make_float4(0.f, 0.f, 0.f, 0.f);
        }
    };
    auto store_A = [&](int st) {
#pragma unroll
        for (int i = 0; i < 4; i++) {
            int idx = tid + i * 256;
            int r = idx >> 3, c4 = idx & 7;
            __half2 h01 = __floats2half2_rn(ar[i].x, ar[i].y);
            __half2 h23 = __floats2half2_rn(ar[i].z, ar[i].w);
            uint2 u;
            u.x = *(uint32_t*)&h01;
            u.y = *(uint32_t*)&h23;
            *(uint2*)(smem + st * STAGE + r * (RS * 2) + c4 * 8) = u;
        }
    };
    auto load_B = [&](int st, int kt) {
        const uint32_t sbs = sb + st * STAGE;
        const int k0 = kt * 32;
#pragma unroll
        for (int idx = tid; idx < NT * 4; idx += 256) {
            int n = idx >> 2, cc = idx & 3;
            size_t go = (size_t)n * KTOT + k0 + cc * 8;
            uint32_t d = sbs + A_BYTES + n * (RS * 2) + cc * 16;
            CP_ASYNC16(d, B + go, 16);
        }
        CP_COMMIT();
    };

    load_A_regs(0);
    load_B(0, 0);
    store_A(0);

    for (int kt = 0; kt < NCH; kt++) {
        if (kt + 1 < NCH) {
            load_A_regs(kt + 1);
            load_B((kt + 1) & 1, kt + 1);
            CP_WAIT1();
        } else {
            CP_WAIT0();
        }
        __syncthreads();

        const uint32_t sbs = sb + (kt & 1) * STAGE;
#pragma unroll
        for (int k16 = 0; k16 < 2; k16++) {
            const int koff = k16 * 16;
            uint32_t af[2][4];
            const int rA = lane & 15;
            const int cA = ((lane >> 4) & 1) * 8 + koff;
#pragma unroll
            for (int mt = 0; mt < 2; mt++) {
                uint32_t ad = sbs + ((m0 + mt * 16 + rA) * RS + cA) * 2;
                LDSM4(af[mt], ad);
            }
            uint32_t bf[NP][4];
            const int rB = ((lane >> 4) << 3) + (lane & 7);
            const int cB = ((lane >> 3) & 1) * 8 + koff;
#pragma unroll
            for (int np = 0; np < NP; np++) {
                uint32_t bd = sbs + A_BYTES + ((n0 + np * 16 + rB) * RS + cB) * 2;
                LDSM4(bf[np], bd);
            }
#pragma unroll
            for (int mt = 0; mt < 2; mt++)
#pragma unroll
                for (int np = 0; np < NP; np++)
#pragma unroll
                    for (int hf = 0; hf < 2; hf++)
                        MMA_FP16(acc[mt][np * 2 + hf], af[mt], bf[np] + hf * 2);
        }
        __syncthreads();
        if (kt + 1 < NCH) store_A((kt + 1) & 1);
    }

#pragma unroll
    for (int mt = 0; mt < 2; mt++) {
        int rw = row0 + m0 + mt * 16 + (lane >> 2);
#pragma unroll
        for (int nt = 0; nt < NT8; nt++) {
            int col = n0 + nt * 8 + (lane & 3) * 2;
            if (rw < M) {
                __half2 h = __floats2half2_rn(acc[mt][nt][0], acc[mt][nt][1]);
                *(__half2*)&Cmat[(size_t)rw * NHID + col] = h;
            }
            if (rw + 8 < M) {
                __half2 h = __floats2half2_rn(acc[mt][nt][2], acc[mt][nt][3]);
                *(__half2*)&Cmat[(size_t)(rw + 8) * NHID + col] = h;
            }
        }
    }
}

// ---------------- fp16 mma.sync GEMM (layers 2/3), C fp16 ----------------
template <int NT, int KTOT>
__global__ void __launch_bounds__(256, 1)
gemm_mma(const __half* __restrict__ A, const __half* __restrict__ B,
         __half* __restrict__ Cmat, int M, int ncols) {
    extern __shared__ char smem[];
    constexpr int NCH = KTOT / 32;
    constexpr int NP  = NT / 32;
    constexpr int NT8 = NT / 16;
    constexpr int A_BYTES = 128 * RS * 2;
    constexpr int B_BYTES = NT * RS * 2;
    constexpr int STAGE = A_BYTES + B_BYTES;

    const uint32_t sb = smem_u32(smem);
    const int tid = threadIdx.x, wid = tid >> 5, lane = tid & 31;
    const int warpM = wid & 3, warpN = wid >> 2;
    const int m0 = warpM * 32, n0 = warpN * (NT / 2);
    const int row0 = blockIdx.x * 128;

    float acc[2][NT8][4];
#pragma unroll
    for (int a = 0; a < 2; a++)
#pragma unroll
        for (int b = 0; b < NT8; b++)
#pragma unroll
            for (int c = 0; c < 4; c++) acc[a][b][c] = 0.f;

    auto load_stage = [&](int st, int kt) {
        const uint32_t sbs = sb + st * STAGE;
        const int k0 = kt * 32;
#pragma unroll
        for (int idx = tid; idx < 512; idx += 256) {
            int r = idx >> 2, cc = idx & 3;
            int gr = row0 + r;
            int sz = (gr < M) ? 16 : 0;
            int rr = (gr < M) ? gr : (M - 1);
            size_t go = (size_t)rr * KTOT + k0 + cc * 8;
            uint32_t d = sbs + r * (RS * 2) + cc * 16;
            CP_ASYNC16(d, A + go, sz);
        }
#pragma unroll
        for (int idx = tid; idx < NT * 4; idx += 256) {
            int n = idx >> 2, cc = idx & 3;
            size_t go = (size_t)n * KTOT + k0 + cc * 8;
            uint32_t d = sbs + A_BYTES + n * (RS * 2) + cc * 16;
            CP_ASYNC16(d, B + go, 16);
        }
        CP_COMMIT();
    };

    load_stage(0, 0);

    for (int kt = 0; kt < NCH; kt++) {
        if (kt + 1 < NCH) {
            load_stage((kt + 1) & 1, kt + 1);
            CP_WAIT1();
        } else {
            CP_WAIT0();
        }
        __syncthreads();

        const uint32_t sbs = sb + (kt & 1) * STAGE;
#pragma unroll
        for (int k16 = 0; k16 < 2; k16++) {
            const int koff = k16 * 16;
            uint32_t af[2][4];
            const int rA = lane & 15;
            const int cA = ((lane >> 4) & 1) * 8 + koff;
#pragma unroll
            for (int mt = 0; mt < 2; mt++) {
                uint32_t ad = sbs + ((m0 + mt * 16 + rA) * RS + cA) * 2;
                LDSM4(af[mt], ad);
            }
            uint32_t bf[NP][4];
            const int rB = ((lane >> 4) << 3) + (lane & 7);
            const int cB = ((lane >> 3) & 1) * 8 + koff;
#pragma unroll
            for (int np = 0; np < NP; np++) {
                uint32_t bd = sbs + A_BYTES + ((n0 + np * 16 + rB) * RS + cB) * 2;
                LDSM4(bf[np], bd);
            }
#pragma unroll
            for (int mt = 0; mt < 2; mt++)
#pragma unroll
                for (int np = 0; np < NP; np++)
#pragma unroll
                    for (int hf = 0; hf < 2; hf++)
                        MMA_FP16(acc[mt][np * 2 + hf], af[mt], bf[np] + hf * 2);
        }
        __syncthreads();
    }

#pragma unroll
    for (int mt = 0; mt < 2; mt++) {
        int rw = row0 + m0 + mt * 16 + (lane >> 2);
#pragma unroll
        for (int nt = 0; nt < NT8; nt++) {
            int col = n0 + nt * 8 + (lane & 3) * 2;
            if (col < ncols) {
                if (rw < M) {
                    __half2 h = __floats2half2_rn(acc[mt][nt][0], acc[mt][nt][1]);
                    *(__half2*)&Cmat[(size_t)rw * ncols + col] = h;
                }
                if (rw + 8 < M) {
                    __half2 h = __floats2half2_rn(acc[mt][nt][2], acc[mt][nt][3]);
                    *(__half2*)&Cmat[(size_t)(rw + 8) * ncols + col] = h;
                }
            }
        }
    }
}

// ---------------- SpMM (CSR gather, fp16 sup) + bias + ReLU -> fp16, F = 128 ----------------
__global__ void spmm128_kernel(const __half* __restrict__ sup, const int* __restrict__ off,
                               const int2* __restrict__ edge, const float* __restrict__ bias,
                               uint2* __restrict__ oh) {
    int warp = (blockIdx.x * blockDim.x + threadIdx.x) >> 5;
    int lane = threadIdx.x & 31;
    if (warp >= NN) return;
    int jb = off[warp], je = off[warp + 1];
    const uint2* sup2 = (const uint2*)sup;  // 4 halves per uint2; 32 per row
    float4 a0 = ((const float4*)bias)[lane];
    float4 a1 = make_float4(0.f, 0.f, 0.f, 0.f);
    float4 a2 = make_float4(0.f, 0.f, 0.f, 0.f);
    float4 a3 = make_float4(0.f, 0.f, 0.f, 0.f);
    int j = jb;
    for (; j + 3 < je; j += 4) {
        int2 e0 = edge[j], e1 = edge[j + 1], e2 = edge[j + 2], e3 = edge[j + 3];
        uint2 u0 = sup2[(size_t)e0.x * 32 + lane];
        uint2 u1 = sup2[(size_t)e1.x * 32 + lane];
        uint2 u2 = sup2[(size_t)e2.x * 32 + lane];
        uint2 u3 = sup2[(size_t)e3.x * 32 + lane];
        float w0 = __int_as_float(e0.y), w1 = __int_as_float(e1.y);
        float w2 = __int_as_float(e2.y), w3 = __int_as_float(e3.y);
        float2 p, q;
        p = __half22float2(*(__half2*)&u0.x); q = __half22float2(*(__half2*)&u0.y);
        a0.x = fmaf(w0, p.x, a0.x); a0.y = fmaf(w0, p.y, a0.y);
        a0.z = fmaf(w0, q.x, a0.z); a0.w = fmaf(w0, q.y, a0.w);
        p = __half22float2(*(__half2*)&u1.x); q = __half22float2(*(__half2*)&u1.y);
        a1.x = fmaf(w1, p.x, a1.x); a1.y = fmaf(w1, p.y, a1.y);
        a1.z = fmaf(w1, q.x, a1.z); a1.w = fmaf(w1, q.y, a1.w);
        p = __half22float2(*(__half2*)&u2.x); q = __half22float2(*(__half2*)&u2.y);
        a2.x = fmaf(w2, p.x, a2.x); a2.y = fmaf(w2, p.y, a2.y);
        a2.z = fmaf(w2, q.x, a2.z); a2.w = fmaf(w2, q.y, a2.w);
        p = __half22float2(*(__half2*)&u3.x); q = __half22float2(*(__half2*)&u3.y);
        a3.x = fmaf(w3, p.x, a3.x); a3.y = fmaf(w3, p.y, a3.y);
        a3.z = fmaf(w3, q.x, a3.z); a3.w = fmaf(w3, q.y, a3.w);
    }
    for (; j < je; j++) {
        int2 e = edge[j];
        float ww = __int_as_float(e.y);
        uint2 u = sup2[(size_t)e.x * 32 + lane];
        float2 p = __half22float2(*(__half2*)&u.x);
        float2 q = __half22float2(*(__half2*)&u.y);
        a0.x = fmaf(ww, p.x, a0.x); a0.y = fmaf(ww, p.y, a0.y);
        a0.z = fmaf(ww, q.x, a0.z); a0.w = fmaf(ww, q.y, a0.w);
    }
    float4 acc;
    acc.x = fmaxf((a0.x + a1.x) + (a2.x + a3.x), 0.f);
    acc.y = fmaxf((a0.y + a1.y) + (a2.y + a3.y), 0.f);
    acc.z = fmaxf((a0.z + a1.z) + (a2.z + a3.z), 0.f);
    acc.w = fmaxf((a0.w + a1.w) + (a2.w + a3.w), 0.f);
    __half2 h01 = __floats2half2_rn(acc.x, acc.y);
    __half2 h23 = __floats2half2_rn(acc.z, acc.w);
    uint2 u;
    u.x = *(uint32_t*)&h01;
    u.y = *(uint32_t*)&h23;
    oh[(size_t)warp * 32 + lane] = u;
}

// ---------------- SpMM F=40 (fp16 sup) + bias + log_softmax ----------------
__global__ void spmm40_ls_kernel(const __half* __restrict__ sup, const int* __restrict__ off,
                                 const int2* __restrict__ edge, const float* __restrict__ b3,
                                 float* __restrict__ out) {
    int node = (blockIdx.x * blockDim.x + threadIdx.x) >> 5;
    int lane = threadIdx.x & 31;
    if (node >= NN) return;
    int jb = off[node], je = off[node + 1];
    float a0 = b3[lane];
    float a1 = (lane < 8) ? b3[32 + lane] : 0.f;
    float c0 = 0.f, c1 = 0.f;
    int j = jb;
    for (; j + 1 < je; j += 2) {
        int2 e0 = edge[j], e1 = edge[j + 1];
        const __half* sp0 = sup + (size_t)e0.x * NCLASS;
        const __half* sp1 = sup + (size_t)e1.x * NCLASS;
        float w0 = __int_as_float(e0.y), w1 = __int_as_float(e1.y);
        float u0 = __half2float(sp0[lane]), u1 = __half2float(sp1[lane]);
        a0 = fmaf(w0, u0, a0);
        c0 = fmaf(w1, u1, c0);
        if (lane < 8) {
            a1 = fmaf(w0, __half2float(sp0[32 + lane]), a1);
            c1 = fmaf(w1, __half2float(sp1[32 + lane]), c1);
        }
    }
    for (; j < je; j++) {
        int2 e = edge[j];
        float ww = __int_as_float(e.y);
        const __half* sp = sup + (size_t)e.x * NCLASS;
        a0 = fmaf(ww, __half2float(sp[lane]), a0);
        if (lane < 8) a1 = fmaf(ww, __half2float(sp[32 + lane]), a1);
    }
    a0 += c0;
    a1 += c1;
    float m = a0;
    if (lane < 8) m = fmaxf(m, a1);
#pragma unroll
    for (int d = 16; d; d >>= 1) m = fmaxf(m, __shfl_xor_sync(0xffffffffu, m, d));
    float sum = expf(a0 - m) + ((lane < 8) ? expf(a1 - m) : 0.f);
#pragma unroll
    for (int d = 16; d; d >>= 1) sum += __shfl_xor_sync(0xffffffffu, sum, d);
    float l = m + logf(sum);
    out[(size_t)node * NCLASS + lane] = a0 - l;
    if (lane < 8) out[(size_t)node * NCLASS + 32 + lane] = a1 - l;
}

// ---------------- launch ----------------
extern "C" void kernel_launch(void* const* d_in, const int* in_sizes, int n_in,
                              void* d_out, int out_size) {
    const float* x  = (const float*)d_in[0];
    const float* ew = (const float*)d_in[1];
    const float* W1 = (const float*)d_in[2];
    const float* b1 = (const float*)d_in[3];
    const float* W2 = (const float*)d_in[4];
    const float* b2 = (const float*)d_in[5];
    const float* W3 = (const float*)d_in[6];
    const float* b3 = (const float*)d_in[7];
    const int* esrc = (const int*)d_in[8];
    const int* edst = (const int*)d_in[9];
    float* out = (float*)d_out;

    __half *sup, *sup3, *hh, *w1, *w2, *w3;
    int *cnt, *off, *cur;
    int2* edge;
    cudaGetSymbolAddress((void**)&sup, g_sup);
    cudaGetSymbolAddress((void**)&sup3, g_sup3);
    cudaGetSymbolAddress((void**)&hh, g_hh);
    cudaGetSymbolAddress((void**)&w1, g_w1);
    cudaGetSymbolAddress((void**)&w2, g_w2);
    cudaGetSymbolAddress((void**)&w3, g_w3);
    cudaGetSymbolAddress((void**)&cnt, g_cnt);
    cudaGetSymbolAddress((void**)&off, g_off);
    cudaGetSymbolAddress((void**)&cur, g_cur);
    cudaGetSymbolAddress((void**)&edge, g_edge);

    const int smem12 = 2 * (10240 + 128 * 80);  // 40960
    const int smem3  = 2 * (10240 + 64 * 80);   // 30720
    cudaFuncSetAttribute(gemm1_mma, cudaFuncAttributeMaxDynamicSharedMemorySize, smem12);
    cudaFuncSetAttribute(gemm_mma<128, 128>, cudaFuncAttributeMaxDynamicSharedMemorySize, smem12);
    cudaFuncSetAttribute(gemm_mma<64, 128>,  cudaFuncAttributeMaxDynamicSharedMemorySize, smem3);

    // persistent side-stream + events (created once; host-side objects only)
    static cudaStream_t s1 = nullptr;
    static cudaEvent_t evFork = nullptr, evJoin = nullptr;
    if (s1 == nullptr) {
        cudaStreamCreateWithFlags(&s1, cudaStreamNonBlocking);
        cudaEventCreateWithFlags(&evFork, cudaEventDisableTiming);
        cudaEventCreateWithFlags(&evJoin, cudaEventDisableTiming);
    }

    // fork: CSR build on s1, dense prep + gemm1 on main stream
    cudaEventRecord(evFork, 0);
    cudaStreamWaitEvent(s1, evFork, 0);
    cudaMemsetAsync(cnt, 0, NN * sizeof(int), s1);
    count_kernel<<<(NE / 2 + 255) / 256, 256, 0, s1>>>(edst, cnt);
    scan_kernel<<<1, 1024, 0, s1>>>(cnt, off, cur);
    scatter_kernel<<<(NE / 2 + 255) / 256, 256, 0, s1>>>(edst, esrc, ew, cur, edge);
    cudaEventRecord(evJoin, s1);

    prep_weights<<<(128 * 256 + 128 * 128 + 64 * 128 + 255) / 256, 256>>>(W1, W2, W3);

    const int gblocks = (NN + 127) / 128;  // 391
    const int spmm_blocks = (NN * 32 + 255) / 256;

    gemm1_mma<<<gblocks, 256, smem12>>>(x, w1, sup, NN);

    // join: spmm needs CSR
    cudaStreamWaitEvent(0, evJoin, 0);

    // PROBE: layer-1 spmm launched twice (idempotent). The measured delta vs
    // the R13 baseline (195.7us) IS the true cost of one spmm128 launch.
    spmm128_kernel<<<spmm_blocks, 256>>>(sup, off, edge, b1, (uint2*)hh);
    spmm128_kernel<<<spmm_blocks, 256>>>(sup, off, edge, b1, (uint2*)hh);
    gemm_mma<128, 128><<<gblocks, 256, smem12>>>(hh, w2, sup, NN, NHID);
    spmm128_kernel<<<spmm_blocks, 256>>>(sup, off, edge, b2, (uint2*)hh);
    gemm_mma<64, 128><<<gblocks, 256, smem3>>>(hh, w3, sup3, NN, NCLASS);
    spmm40_ls_kernel<<<spmm_blocks, 256>>>(sup3, off, edge, b3, out);
}

// round 16
// speedup vs baseline: 1.0790x; 1.0790x over previous
#include <cuda_runtime.h>
#include <cuda_fp16.h>
#include <cuda_bf16.h>
#include <math.h>
#include <stdint.h>

#define NN 50000
#define NE 600000
#define NFEAT 256
#define NHID 128
#define NCLASS 40
#define RS 40  // padded smem row stride in fp16 elems (80B) -> conflict-free ldmatrix

// ---------------- scratch (no allocations allowed) ----------------
__device__ __half g_sup[(size_t)NN * NHID];    // support (h @ W) in fp16
__device__ __half g_sup3[(size_t)NN * NCLASS];
__device__ __half g_hh[(size_t)NN * NHID];
__device__ __half g_w1[128 * 256];
__device__ __half g_w2[128 * 128];
__device__ __half g_w3[64 * 128];
__device__ int  g_cnt[NN];
__device__ int  g_off[NN + 1];
__device__ int  g_cur[NN];
__device__ int2 g_edge[NE];

// ---------------- helpers ----------------
__device__ __forceinline__ uint32_t smem_u32(const void* p) {
    uint32_t a;
    asm("{ .reg .u64 t; cvta.to.shared.u64 t, %1; cvt.u32.u64 %0, t; }" : "=r"(a) : "l"(p));
    return a;
}
#define LDSM4(r, addr) \
    asm volatile("ldmatrix.sync.aligned.m8n8.x4.shared.b16 {%0,%1,%2,%3}, [%4];" \
        : "=r"((r)[0]), "=r"((r)[1]), "=r"((r)[2]), "=r"((r)[3]) : "r"(addr))
#define MMA_FP16(c, a, b) \
    asm volatile("mma.sync.aligned.m16n8k16.row.col.f32.f16.f16.f32 " \
        "{%0,%1,%2,%3}, {%4,%5,%6,%7}, {%8,%9}, {%0,%1,%2,%3};" \
        : "+f"((c)[0]), "+f"((c)[1]), "+f"((c)[2]), "+f"((c)[3]) \
        : "r"((a)[0]), "r"((a)[1]), "r"((a)[2]), "r"((a)[3]), "r"((b)[0]), "r"((b)[1]))
#define CP_ASYNC16(dst, src, sz) \
    asm volatile("cp.async.cg.shared.global [%0], [%1], 16, %2;" \
        :: "r"(dst), "l"(src), "r"(sz))
#define CP_COMMIT() asm volatile("cp.async.commit_group;")
#define CP_WAIT1()  asm volatile("cp.async.wait_group 1;")
#define CP_WAIT0()  asm volatile("cp.async.wait_group 0;")

// ---------------- weight transpose -> fp16, [N][K] ----------------
__global__ void prep_weights(const float* __restrict__ W1, const float* __restrict__ W2,
                             const float* __restrict__ W3) {
    int i = blockIdx.x * blockDim.x + threadIdx.x;
    const int S1 = 128 * 256, S2 = 128 * 128, S3 = 64 * 128;
    float v; __half* dst; int o;
    if (i < S1) {
        int n = i / 256, k = i % 256;
        v = W1[k * 128 + n]; o = i; dst = g_w1;
    } else if (i < S1 + S2) {
        int j = i - S1; int n = j / 128, k = j % 128;
        v = W2[k * 128 + n]; o = j; dst = g_w2;
    } else if (i < S1 + S2 + S3) {
        int j = i - S1 - S2; int n = j / 128, k = j % 128;
        v = (n < NCLASS) ? W3[k * NCLASS + n] : 0.f; o = j; dst = g_w3;
    } else return;
    dst[o] = __float2half(v);
}

// ---------------- CSR build (2 edges/thread) ----------------
__global__ void count_kernel(const int* __restrict__ dst, int* __restrict__ cnt) {
    int i = blockIdx.x * blockDim.x + threadIdx.x;
    if (2 * i >= NE) return;
    int2 d = *(const int2*)&dst[2 * i];
    atomicAdd(&cnt[d.x], 1);
    atomicAdd(&cnt[d.y], 1);
}
__global__ void scan_kernel(const int* __restrict__ cnt, int* __restrict__ off,
                            int* __restrict__ cur) {
    __shared__ int ssum[1024];
    const int t = threadIdx.x;
    const int CH = (NN + 1023) / 1024;
    const int start = t * CH;
    int s = 0;
    for (int j = 0; j < CH; j++) { int i = start + j; if (i < NN) s += cnt[i]; }
    ssum[t] = s;
    __syncthreads();
    for (int d = 1; d < 1024; d <<= 1) {
        int v = (t >= d) ? ssum[t - d] : 0;
        __syncthreads();
        ssum[t] += v;
        __syncthreads();
    }
    int run = (t > 0) ? ssum[t - 1] : 0;
    for (int j = 0; j < CH; j++) {
        int i = start + j;
        if (i < NN) { off[i] = run; cur[i] = run; run += cnt[i]; }
    }
    if (t == 1023) off[NN] = ssum[1023];
}
__global__ void scatter_kernel(const int* __restrict__ dst, const int* __restrict__ src,
                               const float* __restrict__ w, int* __restrict__ cur,
                               int2* __restrict__ edge) {
    int i = blockIdx.x * blockDim.x + threadIdx.x;
    if (2 * i >= NE) return;
    int2 d = *(const int2*)&dst[2 * i];
    int2 s = *(const int2*)&src[2 * i];
    float2 ww = *(const float2*)&w[2 * i];
    int p0 = atomicAdd(&cur[d.x], 1);
    edge[p0] = make_int2(s.x, __float_as_int(ww.x));
    int p1 = atomicAdd(&cur[d.y], 1);
    edge[p1] = make_int2(s.y, __float_as_int(ww.y));
}

// ---------------- GEMM1: A fp32 (x) converted in-kernel, B fp16; C fp16 ----------------
__global__ void __launch_bounds__(256, 1)
gemm1_mma(const float* __restrict__ A, const __half* __restrict__ B,
          __half* __restrict__ Cmat, int M) {
    extern __shared__ char smem[];
    constexpr int KTOT = 256, NT = 128, NCH = 8;
    constexpr int NP  = NT / 32;
    constexpr int NT8 = NT / 16;
    constexpr int A_BYTES = 128 * RS * 2;  // fp16 tile after convert
    constexpr int B_BYTES = NT * RS * 2;
    constexpr int STAGE = A_BYTES + B_BYTES;

    const uint32_t sb = smem_u32(smem);
    const int tid = threadIdx.x, wid = tid >> 5, lane = tid & 31;
    const int warpM = wid & 3, warpN = wid >> 2;
    const int m0 = warpM * 32, n0 = warpN * (NT / 2);
    const int row0 = blockIdx.x * 128;

    float acc[2][NT8][4];
#pragma unroll
    for (int a = 0; a < 2; a++)
#pragma unroll
        for (int b = 0; b < NT8; b++)
#pragma unroll
            for (int c = 0; c < 4; c++) acc[a][b][c] = 0.f;

    float4 ar[4];
    auto load_A_regs = [&](int kt) {
#pragma unroll
        for (int i = 0; i < 4; i++) {
            int idx = tid + i * 256;
            int r = idx >> 3, c4 = idx & 7;
            int gr = row0 + r;
            ar[i] = (gr < M) ? *(const float4*)&A[(size_t)gr * KTOT + kt * 32 + c4 * 4]
                             : make_float4(0.f, 0.f, 0.f, 0.f);
        }
    };
    auto store_A = [&](int st) {
#pragma unroll
        for (int i = 0; i < 4; i++) {
            int idx = tid + i * 256;
            int r = idx >> 3, c4 = idx & 7;
            __half2 h01 = __floats2half2_rn(ar[i].x, ar[i].y);
            __half2 h23 = __floats2half2_rn(ar[i].z, ar[i].w);
            uint2 u;
            u.x = *(uint32_t*)&h01;
            u.y = *(uint32_t*)&h23;
            *(uint2*)(smem + st * STAGE + r * (RS * 2) + c4 * 8) = u;
        }
    };
    auto load_B = [&](int st, int kt) {
        const uint32_t sbs = sb + st * STAGE;
        const int k0 = kt * 32;
#pragma unroll
        for (int idx = tid; idx < NT * 4; idx += 256) {
            int n = idx >> 2, cc = idx & 3;
            size_t go = (size_t)n * KTOT + k0 + cc * 8;
            uint32_t d = sbs + A_BYTES + n * (RS * 2) + cc * 16;
            CP_ASYNC16(d, B + go, 16);
        }
        CP_COMMIT();
    };

    load_A_regs(0);
    load_B(0, 0);
    store_A(0);

    for (int kt = 0; kt < NCH; kt++) {
        if (kt + 1 < NCH) {
            load_A_regs(kt + 1);
            load_B((kt + 1) & 1, kt + 1);
            CP_WAIT1();
        } else {
            CP_WAIT0();
        }
        __syncthreads();

        const uint32_t sbs = sb + (kt & 1) * STAGE;
#pragma unroll
        for (int k16 = 0; k16 < 2; k16++) {
            const int koff = k16 * 16;
            uint32_t af[2][4];
            const int rA = lane & 15;
            const int cA = ((lane >> 4) & 1) * 8 + koff;
#pragma unroll
            for (int mt = 0; mt < 2; mt++) {
                uint32_t ad = sbs + ((m0 + mt * 16 + rA) * RS + cA) * 2;
                LDSM4(af[mt], ad);
            }
            uint32_t bf[NP][4];
            const int rB = ((lane >> 4) << 3) + (lane & 7);
            const int cB = ((lane >> 3) & 1) * 8 + koff;
#pragma unroll
            for (int np = 0; np < NP; np++) {
                uint32_t bd = sbs + A_BYTES + ((n0 + np * 16 + rB) * RS + cB) * 2;
                LDSM4(bf[np], bd);
            }
#pragma unroll
            for (int mt = 0; mt < 2; mt++)
#pragma unroll
                for (int np = 0; np < NP; np++)
#pragma unroll
                    for (int hf = 0; hf < 2; hf++)
                        MMA_FP16(acc[mt][np * 2 + hf], af[mt], bf[np] + hf * 2);
        }
        __syncthreads();
        if (kt + 1 < NCH) store_A((kt + 1) & 1);
    }

#pragma unroll
    for (int mt = 0; mt < 2; mt++) {
        int rw = row0 + m0 + mt * 16 + (lane >> 2);
#pragma unroll
        for (int nt = 0; nt < NT8; nt++) {
            int col = n0 + nt * 8 + (lane & 3) * 2;
            if (rw < M) {
                __half2 h = __floats2half2_rn(acc[mt][nt][0], acc[mt][nt][1]);
                *(__half2*)&Cmat[(size_t)rw * NHID + col] = h;
            }
            if (rw + 8 < M) {
                __half2 h = __floats2half2_rn(acc[mt][nt][2], acc[mt][nt][3]);
                *(__half2*)&Cmat[(size_t)(rw + 8) * NHID + col] = h;
            }
        }
    }
}

// ---------------- fp16 mma.sync GEMM (layers 2/3), C fp16 ----------------
template <int NT, int KTOT>
__global__ void __launch_bounds__(256, 1)
gemm_mma(const __half* __restrict__ A, const __half* __restrict__ B,
         __half* __restrict__ Cmat, int M, int ncols) {
    extern __shared__ char smem[];
    constexpr int NCH = KTOT / 32;
    constexpr int NP  = NT / 32;
    constexpr int NT8 = NT / 16;
    constexpr int A_BYTES = 128 * RS * 2;
    constexpr int B_BYTES = NT * RS * 2;
    constexpr int STAGE = A_BYTES + B_BYTES;

    const uint32_t sb = smem_u32(smem);
    const int tid = threadIdx.x, wid = tid >> 5, lane = tid & 31;
    const int warpM = wid & 3, warpN = wid >> 2;
    const int m0 = warpM * 32, n0 = warpN * (NT / 2);
    const int row0 = blockIdx.x * 128;

    float acc[2][NT8][4];
#pragma unroll
    for (int a = 0; a < 2; a++)
#pragma unroll
        for (int b = 0; b < NT8; b++)
#pragma unroll
            for (int c = 0; c < 4; c++) acc[a][b][c] = 0.f;

    auto load_stage = [&](int st, int kt) {
        const uint32_t sbs = sb + st * STAGE;
        const int k0 = kt * 32;
#pragma unroll
        for (int idx = tid; idx < 512; idx += 256) {
            int r = idx >> 2, cc = idx & 3;
            int gr = row0 + r;
            int sz = (gr < M) ? 16 : 0;
            int rr = (gr < M) ? gr : (M - 1);
            size_t go = (size_t)rr * KTOT + k0 + cc * 8;
            uint32_t d = sbs + r * (RS * 2) + cc * 16;
            CP_ASYNC16(d, A + go, sz);
        }
#pragma unroll
        for (int idx = tid; idx < NT * 4; idx += 256) {
            int n = idx >> 2, cc = idx & 3;
            size_t go = (size_t)n * KTOT + k0 + cc * 8;
            uint32_t d = sbs + A_BYTES + n * (RS * 2) + cc * 16;
            CP_ASYNC16(d, B + go, 16);
        }
        CP_COMMIT();
    };

    load_stage(0, 0);

    for (int kt = 0; kt < NCH; kt++) {
        if (kt + 1 < NCH) {
            load_stage((kt + 1) & 1, kt + 1);
            CP_WAIT1();
        } else {
            CP_WAIT0();
        }
        __syncthreads();

        const uint32_t sbs = sb + (kt & 1) * STAGE;
#pragma unroll
        for (int k16 = 0; k16 < 2; k16++) {
            const int koff = k16 * 16;
            uint32_t af[2][4];
            const int rA = lane & 15;
            const int cA = ((lane >> 4) & 1) * 8 + koff;
#pragma unroll
            for (int mt = 0; mt < 2; mt++) {
                uint32_t ad = sbs + ((m0 + mt * 16 + rA) * RS + cA) * 2;
                LDSM4(af[mt], ad);
            }
            uint32_t bf[NP][4];
            const int rB = ((lane >> 4) << 3) + (lane & 7);
            const int cB = ((lane >> 3) & 1) * 8 + koff;
#pragma unroll
            for (int np = 0; np < NP; np++) {
                uint32_t bd = sbs + A_BYTES + ((n0 + np * 16 + rB) * RS + cB) * 2;
                LDSM4(bf[np], bd);
            }
#pragma unroll
            for (int mt = 0; mt < 2; mt++)
#pragma unroll
                for (int np = 0; np < NP; np++)
#pragma unroll
                    for (int hf = 0; hf < 2; hf++)
                        MMA_FP16(acc[mt][np * 2 + hf], af[mt], bf[np] + hf * 2);
        }
        __syncthreads();
    }

#pragma unroll
    for (int mt = 0; mt < 2; mt++) {
        int rw = row0 + m0 + mt * 16 + (lane >> 2);
#pragma unroll
        for (int nt = 0; nt < NT8; nt++) {
            int col = n0 + nt * 8 + (lane & 3) * 2;
            if (col < ncols) {
                if (rw < M) {
                    __half2 h = __floats2half2_rn(acc[mt][nt][0], acc[mt][nt][1]);
                    *(__half2*)&Cmat[(size_t)rw * ncols + col] = h;
                }
                if (rw + 8 < M) {
                    __half2 h = __floats2half2_rn(acc[mt][nt][2], acc[mt][nt][3]);
                    *(__half2*)&Cmat[(size_t)(rw + 8) * ncols + col] = h;
                }
            }
        }
    }
}

// ---------------- SpMM F=128: TWO warps per node (64 feats each), fp16 sup ----------------
__global__ void spmm128_kernel(const __half* __restrict__ sup, const int* __restrict__ off,
                               const int2* __restrict__ edge, const float* __restrict__ bias,
                               uint32_t* __restrict__ oh) {
    int gw = (blockIdx.x * blockDim.x + threadIdx.x) >> 5;
    int node = gw >> 1;
    int half = gw & 1;
    int lane = threadIdx.x & 31;
    if (node >= NN) return;
    int jb = off[node], je = off[node + 1];
    const uint32_t* sup32 = (const uint32_t*)sup;  // 64 uint32 per row (128 fp16)
    const int fo = half * 32 + lane;               // uint32 index within row

    float2 b = ((const float2*)bias)[fo];
    float2 a0 = b;
    float2 a1 = make_float2(0.f, 0.f);
    float2 a2 = make_float2(0.f, 0.f);
    float2 a3 = make_float2(0.f, 0.f);

    int j = jb;
    for (; j + 3 < je; j += 4) {
        int2 e0 = edge[j], e1 = edge[j + 1], e2 = edge[j + 2], e3 = edge[j + 3];
        uint32_t u0 = sup32[(size_t)e0.x * 64 + fo];
        uint32_t u1 = sup32[(size_t)e1.x * 64 + fo];
        uint32_t u2 = sup32[(size_t)e2.x * 64 + fo];
        uint32_t u3 = sup32[(size_t)e3.x * 64 + fo];
        float w0 = __int_as_float(e0.y), w1 = __int_as_float(e1.y);
        float w2 = __int_as_float(e2.y), w3 = __int_as_float(e3.y);
        float2 p;
        p = __half22float2(*(__half2*)&u0);
        a0.x = fmaf(w0, p.x, a0.x); a0.y = fmaf(w0, p.y, a0.y);
        p = __half22float2(*(__half2*)&u1);
        a1.x = fmaf(w1, p.x, a1.x); a1.y = fmaf(w1, p.y, a1.y);
        p = __half22float2(*(__half2*)&u2);
        a2.x = fmaf(w2, p.x, a2.x); a2.y = fmaf(w2, p.y, a2.y);
        p = __half22float2(*(__half2*)&u3);
        a3.x = fmaf(w3, p.x, a3.x); a3.y = fmaf(w3, p.y, a3.y);
    }
    for (; j < je; j++) {
        int2 e = edge[j];
        float ww = __int_as_float(e.y);
        uint32_t u = sup32[(size_t)e.x * 64 + fo];
        float2 p = __half22float2(*(__half2*)&u);
        a0.x = fmaf(ww, p.x, a0.x); a0.y = fmaf(ww, p.y, a0.y);
    }
    float2 r;
    r.x = fmaxf((a0.x + a1.x) + (a2.x + a3.x), 0.f);
    r.y = fmaxf((a0.y + a1.y) + (a2.y + a3.y), 0.f);
    __half2 h = __floats2half2_rn(r.x, r.y);
    oh[(size_t)node * 64 + fo] = *(uint32_t*)&h;
}

// ---------------- SpMM F=40 (fp16 sup) + bias + log_softmax ----------------
__global__ void spmm40_ls_kernel(const __half* __restrict__ sup, const int* __restrict__ off,
                                 const int2* __restrict__ edge, const float* __restrict__ b3,
                                 float* __restrict__ out) {
    int node = (blockIdx.x * blockDim.x + threadIdx.x) >> 5;
    int lane = threadIdx.x & 31;
    if (node >= NN) return;
    int jb = off[node], je = off[node + 1];
    float a0 = b3[lane];
    float a1 = (lane < 8) ? b3[32 + lane] : 0.f;
    float c0 = 0.f, c1 = 0.f;
    int j = jb;
    for (; j + 1 < je; j += 2) {
        int2 e0 = edge[j], e1 = edge[j + 1];
        const __half* sp0 = sup + (size_t)e0.x * NCLASS;
        const __half* sp1 = sup + (size_t)e1.x * NCLASS;
        float w0 = __int_as_float(e0.y), w1 = __int_as_float(e1.y);
        float u0 = __half2float(sp0[lane]), u1 = __half2float(sp1[lane]);
        a0 = fmaf(w0, u0, a0);
        c0 = fmaf(w1, u1, c0);
        if (lane < 8) {
            a1 = fmaf(w0, __half2float(sp0[32 + lane]), a1);
            c1 = fmaf(w1, __half2float(sp1[32 + lane]), c1);
        }
    }
    for (; j < je; j++) {
        int2 e = edge[j];
        float ww = __int_as_float(e.y);
        const __half* sp = sup + (size_t)e.x * NCLASS;
        a0 = fmaf(ww, __half2float(sp[lane]), a0);
        if (lane < 8) a1 = fmaf(ww, __half2float(sp[32 + lane]), a1);
    }
    a0 += c0;
    a1 += c1;
    float m = a0;
    if (lane < 8) m = fmaxf(m, a1);
#pragma unroll
    for (int d = 16; d; d >>= 1) m = fmaxf(m, __shfl_xor_sync(0xffffffffu, m, d));
    float sum = expf(a0 - m) + ((lane < 8) ? expf(a1 - m) : 0.f);
#pragma unroll
    for (int d = 16; d; d >>= 1) sum += __shfl_xor_sync(0xffffffffu, sum, d);
    float l = m + logf(sum);
    out[(size_t)node * NCLASS + lane] = a0 - l;
    if (lane < 8) out[(size_t)node * NCLASS + 32 + lane] = a1 - l;
}

// ---------------- launch ----------------
extern "C" void kernel_launch(void* const* d_in, const int* in_sizes, int n_in,
                              void* d_out, int out_size) {
    const float* x  = (const float*)d_in[0];
    const float* ew = (const float*)d_in[1];
    const float* W1 = (const float*)d_in[2];
    const float* b1 = (const float*)d_in[3];
    const float* W2 = (const float*)d_in[4];
    const float* b2 = (const float*)d_in[5];
    const float* W3 = (const float*)d_in[6];
    const float* b3 = (const float*)d_in[7];
    const int* esrc = (const int*)d_in[8];
    const int* edst = (const int*)d_in[9];
    float* out = (float*)d_out;

    __half *sup, *sup3, *hh, *w1, *w2, *w3;
    int *cnt, *off, *cur;
    int2* edge;
    cudaGetSymbolAddress((void**)&sup, g_sup);
    cudaGetSymbolAddress((void**)&sup3, g_sup3);
    cudaGetSymbolAddress((void**)&hh, g_hh);
    cudaGetSymbolAddress((void**)&w1, g_w1);
    cudaGetSymbolAddress((void**)&w2, g_w2);
    cudaGetSymbolAddress((void**)&w3, g_w3);
    cudaGetSymbolAddress((void**)&cnt, g_cnt);
    cudaGetSymbolAddress((void**)&off, g_off);
    cudaGetSymbolAddress((void**)&cur, g_cur);
    cudaGetSymbolAddress((void**)&edge, g_edge);

    const int smem12 = 2 * (10240 + 128 * 80);  // 40960
    const int smem3  = 2 * (10240 + 64 * 80);   // 30720
    cudaFuncSetAttribute(gemm1_mma, cudaFuncAttributeMaxDynamicSharedMemorySize, smem12);
    cudaFuncSetAttribute(gemm_mma<128, 128>, cudaFuncAttributeMaxDynamicSharedMemorySize, smem12);
    cudaFuncSetAttribute(gemm_mma<64, 128>,  cudaFuncAttributeMaxDynamicSharedMemorySize, smem3);

    // persistent side-stream + events (created once; host-side objects only)
    static cudaStream_t s1 = nullptr;
    static cudaEvent_t evFork = nullptr, evJoin = nullptr;
    if (s1 == nullptr) {
        cudaStreamCreateWithFlags(&s1, cudaStreamNonBlocking);
        cudaEventCreateWithFlags(&evFork, cudaEventDisableTiming);
        cudaEventCreateWithFlags(&evJoin, cudaEventDisableTiming);
    }

    // fork: CSR build on s1, dense prep + gemm1 on main stream
    cudaEventRecord(evFork, 0);
    cudaStreamWaitEvent(s1, evFork, 0);
    cudaMemsetAsync(cnt, 0, NN * sizeof(int), s1);
    count_kernel<<<(NE / 2 + 255) / 256, 256, 0, s1>>>(edst, cnt);
    scan_kernel<<<1, 1024, 0, s1>>>(cnt, off, cur);
    scatter_kernel<<<(NE / 2 + 255) / 256, 256, 0, s1>>>(edst, esrc, ew, cur, edge);
    cudaEventRecord(evJoin, s1);

    prep_weights<<<(128 * 256 + 128 * 128 + 64 * 128 + 255) / 256, 256>>>(W1, W2, W3);

    const int gblocks = (NN + 127) / 128;  // 391
    const int spmm_blocks  = (NN * 64 + 255) / 256;   // 2 warps/node
    const int spmm40_blocks = (NN * 32 + 255) / 256;  // 1 warp/node

    gemm1_mma<<<gblocks, 256, smem12>>>(x, w1, sup, NN);

    // join: spmm needs CSR
    cudaStreamWaitEvent(0, evJoin, 0);

    spmm128_kernel<<<spmm_blocks, 256>>>(sup, off, edge, b1, (uint32_t*)hh);
    gemm_mma<128, 128><<<gblocks, 256, smem12>>>(hh, w2, sup, NN, NHID);
    spmm128_kernel<<<spmm_blocks, 256>>>(sup, off, edge, b2, (uint32_t*)hh);
    gemm_mma<64, 128><<<gblocks, 256, smem3>>>(hh, w3, sup3, NN, NCLASS);
    spmm40_ls_kernel<<<spmm40_blocks, 256>>>(sup3, off, edge, b3, out);
}

// round 17
// speedup vs baseline: 1.1863x; 1.0995x over previous
#include <cuda_runtime.h>
#include <cuda_fp16.h>
#include <cuda_bf16.h>
#include <math.h>
#include <stdint.h>

#define NN 50000
#define NE 600000
#define NFEAT 256
#define NHID 128
#define NCLASS 40
#define RS 40  // padded smem row stride in fp16 elems (80B) -> conflict-free ldmatrix

// ---------------- scratch (no allocations allowed) ----------------
__device__ __half g_sup[(size_t)NN * NHID];    // support (h @ W) in fp16
__device__ __half g_sup3[(size_t)NN * NCLASS];
__device__ __half g_hh[(size_t)NN * NHID];
__device__ __half g_w1[128 * 256];
__device__ __half g_w2[128 * 128];
__device__ __half g_w3[64 * 128];
__device__ int  g_cnt[NN];
__device__ int  g_off[NN + 1];
__device__ int  g_cur[NN];
__device__ int2 g_edge[NE];

// ---------------- helpers ----------------
__device__ __forceinline__ uint32_t smem_u32(const void* p) {
    uint32_t a;
    asm("{ .reg .u64 t; cvta.to.shared.u64 t, %1; cvt.u32.u64 %0, t; }" : "=r"(a) : "l"(p));
    return a;
}
#define LDSM4(r, addr) \
    asm volatile("ldmatrix.sync.aligned.m8n8.x4.shared.b16 {%0,%1,%2,%3}, [%4];" \
        : "=r"((r)[0]), "=r"((r)[1]), "=r"((r)[2]), "=r"((r)[3]) : "r"(addr))
#define MMA_FP16(c, a, b) \
    asm volatile("mma.sync.aligned.m16n8k16.row.col.f32.f16.f16.f32 " \
        "{%0,%1,%2,%3}, {%4,%5,%6,%7}, {%8,%9}, {%0,%1,%2,%3};" \
        : "+f"((c)[0]), "+f"((c)[1]), "+f"((c)[2]), "+f"((c)[3]) \
        : "r"((a)[0]), "r"((a)[1]), "r"((a)[2]), "r"((a)[3]), "r"((b)[0]), "r"((b)[1]))
#define CP_ASYNC16(dst, src, sz) \
    asm volatile("cp.async.cg.shared.global [%0], [%1], 16, %2;" \
        :: "r"(dst), "l"(src), "r"(sz))
#define CP_COMMIT() asm volatile("cp.async.commit_group;")
#define CP_WAIT1()  asm volatile("cp.async.wait_group 1;")
#define CP_WAIT0()  asm volatile("cp.async.wait_group 0;")

// ---------------- weight transpose -> fp16, [N][K] ----------------
__global__ void prep_weights(const float* __restrict__ W1, const float* __restrict__ W2,
                             const float* __restrict__ W3) {
    int i = blockIdx.x * blockDim.x + threadIdx.x;
    const int S1 = 128 * 256, S2 = 128 * 128, S3 = 64 * 128;
    float v; __half* dst; int o;
    if (i < S1) {
        int n = i / 256, k = i % 256;
        v = W1[k * 128 + n]; o = i; dst = g_w1;
    } else if (i < S1 + S2) {
        int j = i - S1; int n = j / 128, k = j % 128;
        v = W2[k * 128 + n]; o = j; dst = g_w2;
    } else if (i < S1 + S2 + S3) {
        int j = i - S1 - S2; int n = j / 128, k = j % 128;
        v = (n < NCLASS) ? W3[k * NCLASS + n] : 0.f; o = j; dst = g_w3;
    } else return;
    dst[o] = __float2half(v);
}

// ---------------- CSR build (2 edges/thread) ----------------
__global__ void count_kernel(const int* __restrict__ dst, int* __restrict__ cnt) {
    int i = blockIdx.x * blockDim.x + threadIdx.x;
    if (2 * i >= NE) return;
    int2 d = *(const int2*)&dst[2 * i];
    atomicAdd(&cnt[d.x], 1);
    atomicAdd(&cnt[d.y], 1);
}
__global__ void scan_kernel(const int* __restrict__ cnt, int* __restrict__ off,
                            int* __restrict__ cur) {
    __shared__ int ssum[1024];
    const int t = threadIdx.x;
    const int CH = (NN + 1023) / 1024;
    const int start = t * CH;
    int s = 0;
    for (int j = 0; j < CH; j++) { int i = start + j; if (i < NN) s += cnt[i]; }
    ssum[t] = s;
    __syncthreads();
    for (int d = 1; d < 1024; d <<= 1) {
        int v = (t >= d) ? ssum[t - d] : 0;
        __syncthreads();
        ssum[t] += v;
        __syncthreads();
    }
    int run = (t > 0) ? ssum[t - 1] : 0;
    for (int j = 0; j < CH; j++) {
        int i = start + j;
        if (i < NN) { off[i] = run; cur[i] = run; run += cnt[i]; }
    }
    if (t == 1023) off[NN] = ssum[1023];
}
__global__ void scatter_kernel(const int* __restrict__ dst, const int* __restrict__ src,
                               const float* __restrict__ w, int* __restrict__ cur,
                               int2* __restrict__ edge) {
    int i = blockIdx.x * blockDim.x + threadIdx.x;
    if (2 * i >= NE) return;
    int2 d = *(const int2*)&dst[2 * i];
    int2 s = *(const int2*)&src[2 * i];
    float2 ww = *(const float2*)&w[2 * i];
    int p0 = atomicAdd(&cur[d.x], 1);
    edge[p0] = make_int2(s.x, __float_as_int(ww.x));
    int p1 = atomicAdd(&cur[d.y], 1);
    edge[p1] = make_int2(s.y, __float_as_int(ww.y));
}

// ---------------- GEMM1: A fp32 (x) converted in-kernel, B fp16; C fp16 ----------------
__global__ void __launch_bounds__(256, 2)
gemm1_mma(const float* __restrict__ A, const __half* __restrict__ B,
          __half* __restrict__ Cmat, int M) {
    extern __shared__ char smem[];
    constexpr int KTOT = 256, NT = 128, NCH = 8;
    constexpr int NP  = NT / 32;
    constexpr int NT8 = NT / 16;
    constexpr int A_BYTES = 128 * RS * 2;  // fp16 tile after convert
    constexpr int B_BYTES = NT * RS * 2;
    constexpr int STAGE = A_BYTES + B_BYTES;

    const uint32_t sb = smem_u32(smem);
    const int tid = threadIdx.x, wid = tid >> 5, lane = tid & 31;
    const int warpM = wid & 3, warpN = wid >> 2;
    const int m0 = warpM * 32, n0 = warpN * (NT / 2);
    const int row0 = blockIdx.x * 128;

    float acc[2][NT8][4];
#pragma unroll
    for (int a = 0; a < 2; a++)
#pragma unroll
        for (int b = 0; b < NT8; b++)
#pragma unroll
            for (int c = 0; c < 4; c++) acc[a][b][c] = 0.f;

    float4 ar[4];
    auto load_A_regs = [&](int kt) {
#pragma unroll
        for (int i = 0; i < 4; i++) {
            int idx = tid + i * 256;
            int r = idx >> 3, c4 = idx & 7;
            int gr = row0 + r;
            ar[i] = (gr < M) ? *(const float4*)&A[(size_t)gr * KTOT + kt * 32 + c4 * 4]
                             : make_float4(0.f, 0.f, 0.f, 0.f);
        }
    };
    auto store_A = [&](int st) {
#pragma unroll
        for (int i = 0; i < 4; i++) {
            int idx = tid + i * 256;
            int r = idx >> 3, c4 = idx & 7;
            __half2 h01 = __floats2half2_rn(ar[i].x, ar[i].y);
            __half2 h23 = __floats2half2_rn(ar[i].z, ar[i].w);
            uint2 u;
            u.x = *(uint32_t*)&h01;
            u.y = *(uint32_t*)&h23;
            *(uint2*)(smem + st * STAGE + r * (RS * 2) + c4 * 8) = u;
        }
    };
    auto load_B = [&](int st, int kt) {
        const uint32_t sbs = sb + st * STAGE;
        const int k0 = kt * 32;
#pragma unroll
        for (int idx = tid; idx < NT * 4; idx += 256) {
            int n = idx >> 2, cc = idx & 3;
            size_t go = (size_t)n * KTOT + k0 + cc * 8;
            uint32_t d = sbs + A_BYTES + n * (RS * 2) + cc * 16;
            CP_ASYNC16(d, B + go, 16);
        }
        CP_COMMIT();
    };

    load_A_regs(0);
    load_B(0, 0);
    store_A(0);

    for (int kt = 0; kt < NCH; kt++) {
        if (kt + 1 < NCH) {
            load_A_regs(kt + 1);
            load_B((kt + 1) & 1, kt + 1);
            CP_WAIT1();
        } else {
            CP_WAIT0();
        }
        __syncthreads();

        const uint32_t sbs = sb + (kt & 1) * STAGE;
#pragma unroll
        for (int k16 = 0; k16 < 2; k16++) {
            const int koff = k16 * 16;
            uint32_t af[2][4];
            const int rA = lane & 15;
            const int cA = ((lane >> 4) & 1) * 8 + koff;
#pragma unroll
            for (int mt = 0; mt < 2; mt++) {
                uint32_t ad = sbs + ((m0 + mt * 16 + rA) * RS + cA) * 2;
                LDSM4(af[mt], ad);
            }
            uint32_t bf[NP][4];
            const int rB = ((lane >> 4) << 3) + (lane & 7);
            const int cB = ((lane >> 3) & 1) * 8 + koff;
#pragma unroll
            for (int np = 0; np < NP; np++) {
                uint32_t bd = sbs + A_BYTES + ((n0 + np * 16 + rB) * RS + cB) * 2;
                LDSM4(bf[np], bd);
            }
#pragma unroll
            for (int mt = 0; mt < 2; mt++)
#pragma unroll
                for (int np = 0; np < NP; np++)
#pragma unroll
                    for (int hf = 0; hf < 2; hf++)
                        MMA_FP16(acc[mt][np * 2 + hf], af[mt], bf[np] + hf * 2);
        }
        __syncthreads();
        if (kt + 1 < NCH) store_A((kt + 1) & 1);
    }

#pragma unroll
    for (int mt = 0; mt < 2; mt++) {
        int rw = row0 + m0 + mt * 16 + (lane >> 2);
#pragma unroll
        for (int nt = 0; nt < NT8; nt++) {
            int col = n0 + nt * 8 + (lane & 3) * 2;
            if (rw < M) {
                __half2 h = __floats2half2_rn(acc[mt][nt][0], acc[mt][nt][1]);
                *(__half2*)&Cmat[(size_t)rw * NHID + col] = h;
            }
            if (rw + 8 < M) {
                __half2 h = __floats2half2_rn(acc[mt][nt][2], acc[mt][nt][3]);
                *(__half2*)&Cmat[(size_t)(rw + 8) * NHID + col] = h;
            }
        }
    }
}

// ---------------- fp16 mma.sync GEMM (layers 2/3), C fp16 ----------------
template <int NT, int KTOT>
__global__ void __launch_bounds__(256, 2)
gemm_mma(const __half* __restrict__ A, const __half* __restrict__ B,
         __half* __restrict__ Cmat, int M, int ncols) {
    extern __shared__ char smem[];
    constexpr int NCH = KTOT / 32;
    constexpr int NP  = NT / 32;
    constexpr int NT8 = NT / 16;
    constexpr int A_BYTES = 128 * RS * 2;
    constexpr int B_BYTES = NT * RS * 2;
    constexpr int STAGE = A_BYTES + B_BYTES;

    const uint32_t sb = smem_u32(smem);
    const int tid = threadIdx.x, wid = tid >> 5, lane = tid & 31;
    const int warpM = wid & 3, warpN = wid >> 2;
    const int m0 = warpM * 32, n0 = warpN * (NT / 2);
    const int row0 = blockIdx.x * 128;

    float acc[2][NT8][4];
#pragma unroll
    for (int a = 0; a < 2; a++)
#pragma unroll
        for (int b = 0; b < NT8; b++)
#pragma unroll
            for (int c = 0; c < 4; c++) acc[a][b][c] = 0.f;

    auto load_stage = [&](int st, int kt) {
        const uint32_t sbs = sb + st * STAGE;
        const int k0 = kt * 32;
#pragma unroll
        for (int idx = tid; idx < 512; idx += 256) {
            int r = idx >> 2, cc = idx & 3;
            int gr = row0 + r;
            int sz = (gr < M) ? 16 : 0;
            int rr = (gr < M) ? gr : (M - 1);
            size_t go = (size_t)rr * KTOT + k0 + cc * 8;
            uint32_t d = sbs + r * (RS * 2) + cc * 16;
            CP_ASYNC16(d, A + go, sz);
        }
#pragma unroll
        for (int idx = tid; idx < NT * 4; idx += 256) {
            int n = idx >> 2, cc = idx & 3;
            size_t go = (size_t)n * KTOT + k0 + cc * 8;
            uint32_t d = sbs + A_BYTES + n * (RS * 2) + cc * 16;
            CP_ASYNC16(d, B + go, 16);
        }
        CP_COMMIT();
    };

    load_stage(0, 0);

    for (int kt = 0; kt < NCH; kt++) {
        if (kt + 1 < NCH) {
            load_stage((kt + 1) & 1, kt + 1);
            CP_WAIT1();
        } else {
            CP_WAIT0();
        }
        __syncthreads();

        const uint32_t sbs = sb + (kt & 1) * STAGE;
#pragma unroll
        for (int k16 = 0; k16 < 2; k16++) {
            const int koff = k16 * 16;
            uint32_t af[2][4];
            const int rA = lane & 15;
            const int cA = ((lane >> 4) & 1) * 8 + koff;
#pragma unroll
            for (int mt = 0; mt < 2; mt++) {
                uint32_t ad = sbs + ((m0 + mt * 16 + rA) * RS + cA) * 2;
                LDSM4(af[mt], ad);
            }
            uint32_t bf[NP][4];
            const int rB = ((lane >> 4) << 3) + (lane & 7);
            const int cB = ((lane >> 3) & 1) * 8 + koff;
#pragma unroll
            for (int np = 0; np < NP; np++) {
                uint32_t bd = sbs + A_BYTES + ((n0 + np * 16 + rB) * RS + cB) * 2;
                LDSM4(bf[np], bd);
            }
#pragma unroll
            for (int mt = 0; mt < 2; mt++)
#pragma unroll
                for (int np = 0; np < NP; np++)
#pragma unroll
                    for (int hf = 0; hf < 2; hf++)
                        MMA_FP16(acc[mt][np * 2 + hf], af[mt], bf[np] + hf * 2);
        }
        __syncthreads();
    }

#pragma unroll
    for (int mt = 0; mt < 2; mt++) {
        int rw = row0 + m0 + mt * 16 + (lane >> 2);
#pragma unroll
        for (int nt = 0; nt < NT8; nt++) {
            int col = n0 + nt * 8 + (lane & 3) * 2;
            if (col < ncols) {
                if (rw < M) {
                    __half2 h = __floats2half2_rn(acc[mt][nt][0], acc[mt][nt][1]);
                    *(__half2*)&Cmat[(size_t)rw * ncols + col] = h;
                }
                if (rw + 8 < M) {
                    __half2 h = __floats2half2_rn(acc[mt][nt][2], acc[mt][nt][3]);
                    *(__half2*)&Cmat[(size_t)(rw + 8) * ncols + col] = h;
                }
            }
        }
    }
}

// ---------------- SpMM (CSR gather, fp16 sup) + bias + ReLU -> fp16, F = 128 ----------------
__global__ void spmm128_kernel(const __half* __restrict__ sup, const int* __restrict__ off,
                               const int2* __restrict__ edge, const float* __restrict__ bias,
                               uint2* __restrict__ oh) {
    int warp = (blockIdx.x * blockDim.x + threadIdx.x) >> 5;
    int lane = threadIdx.x & 31;
    if (warp >= NN) return;
    int jb = off[warp], je = off[warp + 1];
    const uint2* sup2 = (const uint2*)sup;  // 4 halves per uint2; 32 per row
    float4 a0 = ((const float4*)bias)[lane];
    float4 a1 = make_float4(0.f, 0.f, 0.f, 0.f);
    float4 a2 = make_float4(0.f, 0.f, 0.f, 0.f);
    float4 a3 = make_float4(0.f, 0.f, 0.f, 0.f);
    int j = jb;
    for (; j + 3 < je; j += 4) {
        int2 e0 = edge[j], e1 = edge[j + 1], e2 = edge[j + 2], e3 = edge[j + 3];
        uint2 u0 = sup2[(size_t)e0.x * 32 + lane];
        uint2 u1 = sup2[(size_t)e1.x * 32 + lane];
        uint2 u2 = sup2[(size_t)e2.x * 32 + lane];
        uint2 u3 = sup2[(size_t)e3.x * 32 + lane];
        float w0 = __int_as_float(e0.y), w1 = __int_as_float(e1.y);
        float w2 = __int_as_float(e2.y), w3 = __int_as_float(e3.y);
        float2 p, q;
        p = __half22float2(*(__half2*)&u0.x); q = __half22float2(*(__half2*)&u0.y);
        a0.x = fmaf(w0, p.x, a0.x); a0.y = fmaf(w0, p.y, a0.y);
        a0.z = fmaf(w0, q.x, a0.z); a0.w = fmaf(w0, q.y, a0.w);
        p = __half22float2(*(__half2*)&u1.x); q = __half22float2(*(__half2*)&u1.y);
        a1.x = fmaf(w1, p.x, a1.x); a1.y = fmaf(w1, p.y, a1.y);
        a1.z = fmaf(w1, q.x, a1.z); a1.w = fmaf(w1, q.y, a1.w);
        p = __half22float2(*(__half2*)&u2.x); q = __half22float2(*(__half2*)&u2.y);
        a2.x = fmaf(w2, p.x, a2.x); a2.y = fmaf(w2, p.y, a2.y);
        a2.z = fmaf(w2, q.x, a2.z); a2.w = fmaf(w2, q.y, a2.w);
        p = __half22float2(*(__half2*)&u3.x); q = __half22float2(*(__half2*)&u3.y);
        a3.x = fmaf(w3, p.x, a3.x); a3.y = fmaf(w3, p.y, a3.y);
        a3.z = fmaf(w3, q.x, a3.z); a3.w = fmaf(w3, q.y, a3.w);
    }
    for (; j < je; j++) {
        int2 e = edge[j];
        float ww = __int_as_float(e.y);
        uint2 u = sup2[(size_t)e.x * 32 + lane];
        float2 p = __half22float2(*(__half2*)&u.x);
        float2 q = __half22float2(*(__half2*)&u.y);
        a0.x = fmaf(ww, p.x, a0.x); a0.y = fmaf(ww, p.y, a0.y);
        a0.z = fmaf(ww, q.x, a0.z); a0.w = fmaf(ww, q.y, a0.w);
    }
    float4 acc;
    acc.x = fmaxf((a0.x + a1.x) + (a2.x + a3.x), 0.f);
    acc.y = fmaxf((a0.y + a1.y) + (a2.y + a3.y), 0.f);
    acc.z = fmaxf((a0.z + a1.z) + (a2.z + a3.z), 0.f);
    acc.w = fmaxf((a0.w + a1.w) + (a2.w + a3.w), 0.f);
    __half2 h01 = __floats2half2_rn(acc.x, acc.y);
    __half2 h23 = __floats2half2_rn(acc.z, acc.w);
    uint2 u;
    u.x = *(uint32_t*)&h01;
    u.y = *(uint32_t*)&h23;
    oh[(size_t)warp * 32 + lane] = u;
}

// ---------------- SpMM F=40 (fp16 sup) + bias + log_softmax ----------------
__global__ void spmm40_ls_kernel(const __half* __restrict__ sup, const int* __restrict__ off,
                                 const int2* __restrict__ edge, const float* __restrict__ b3,
                                 float* __restrict__ out) {
    int node = (blockIdx.x * blockDim.x + threadIdx.x) >> 5;
    int lane = threadIdx.x & 31;
    if (node >= NN) return;
    int jb = off[node], je = off[node + 1];
    float a0 = b3[lane];
    float a1 = (lane < 8) ? b3[32 + lane] : 0.f;
    float c0 = 0.f, c1 = 0.f;
    int j = jb;
    for (; j + 1 < je; j += 2) {
        int2 e0 = edge[j], e1 = edge[j + 1];
        const __half* sp0 = sup + (size_t)e0.x * NCLASS;
        const __half* sp1 = sup + (size_t)e1.x * NCLASS;
        float w0 = __int_as_float(e0.y), w1 = __int_as_float(e1.y);
        float u0 = __half2float(sp0[lane]), u1 = __half2float(sp1[lane]);
        a0 = fmaf(w0, u0, a0);
        c0 = fmaf(w1, u1, c0);
        if (lane < 8) {
            a1 = fmaf(w0, __half2float(sp0[32 + lane]), a1);
            c1 = fmaf(w1, __half2float(sp1[32 + lane]), c1);
        }
    }
    for (; j < je; j++) {
        int2 e = edge[j];
        float ww = __int_as_float(e.y);
        const __half* sp = sup + (size_t)e.x * NCLASS;
        a0 = fmaf(ww, __half2float(sp[lane]), a0);
        if (lane < 8) a1 = fmaf(ww, __half2float(sp[32 + lane]), a1);
    }
    a0 += c0;
    a1 += c1;
    float m = a0;
    if (lane < 8) m = fmaxf(m, a1);
#pragma unroll
    for (int d = 16; d; d >>= 1) m = fmaxf(m, __shfl_xor_sync(0xffffffffu, m, d));
    float sum = expf(a0 - m) + ((lane < 8) ? expf(a1 - m) : 0.f);
#pragma unroll
    for (int d = 16; d; d >>= 1) sum += __shfl_xor_sync(0xffffffffu, sum, d);
    float l = m + logf(sum);
    out[(size_t)node * NCLASS + lane] = a0 - l;
    if (lane < 8) out[(size_t)node * NCLASS + 32 + lane] = a1 - l;
}

// ---------------- launch ----------------
extern "C" void kernel_launch(void* const* d_in, const int* in_sizes, int n_in,
                              void* d_out, int out_size) {
    const float* x  = (const float*)d_in[0];
    const float* ew = (const float*)d_in[1];
    const float* W1 = (const float*)d_in[2];
    const float* b1 = (const float*)d_in[3];
    const float* W2 = (const float*)d_in[4];
    const float* b2 = (const float*)d_in[5];
    const float* W3 = (const float*)d_in[6];
    const float* b3 = (const float*)d_in[7];
    const int* esrc = (const int*)d_in[8];
    const int* edst = (const int*)d_in[9];
    float* out = (float*)d_out;

    __half *sup, *sup3, *hh, *w1, *w2, *w3;
    int *cnt, *off, *cur;
    int2* edge;
    cudaGetSymbolAddress((void**)&sup, g_sup);
    cudaGetSymbolAddress((void**)&sup3, g_sup3);
    cudaGetSymbolAddress((void**)&hh, g_hh);
    cudaGetSymbolAddress((void**)&w1, g_w1);
    cudaGetSymbolAddress((void**)&w2, g_w2);
    cudaGetSymbolAddress((void**)&w3, g_w3);
    cudaGetSymbolAddress((void**)&cnt, g_cnt);
    cudaGetSymbolAddress((void**)&off, g_off);
    cudaGetSymbolAddress((void**)&cur, g_cur);
    cudaGetSymbolAddress((void**)&edge, g_edge);

    const int smem12 = 2 * (10240 + 128 * 80);  // 40960
    const int smem3  = 2 * (10240 + 64 * 80);   // 30720
    cudaFuncSetAttribute(gemm1_mma, cudaFuncAttributeMaxDynamicSharedMemorySize, smem12);
    cudaFuncSetAttribute(gemm_mma<128, 128>, cudaFuncAttributeMaxDynamicSharedMemorySize, smem12);
    cudaFuncSetAttribute(gemm_mma<64, 128>,  cudaFuncAttributeMaxDynamicSharedMemorySize, smem3);

    // persistent side-stream + events (created once; host-side objects only)
    static cudaStream_t s1 = nullptr;
    static cudaEvent_t evFork = nullptr, evJoin = nullptr;
    if (s1 == nullptr) {
        cudaStreamCreateWithFlags(&s1, cudaStreamNonBlocking);
        cudaEventCreateWithFlags(&evFork, cudaEventDisableTiming);
        cudaEventCreateWithFlags(&evJoin, cudaEventDisableTiming);
    }

    // fork: CSR build on s1, dense prep + gemm1 on main stream
    cudaEventRecord(evFork, 0);
    cudaStreamWaitEvent(s1, evFork, 0);
    cudaMemsetAsync(cnt, 0, NN * sizeof(int), s1);
    count_kernel<<<(NE / 2 + 255) / 256, 256, 0, s1>>>(edst, cnt);
    scan_kernel<<<1, 1024, 0, s1>>>(cnt, off, cur);
    scatter_kernel<<<(NE / 2 + 255) / 256, 256, 0, s1>>>(edst, esrc, ew, cur, edge);
    cudaEventRecord(evJoin, s1);

    prep_weights<<<(128 * 256 + 128 * 128 + 64 * 128 + 255) / 256, 256>>>(W1, W2, W3);

    const int gblocks = (NN + 127) / 128;  // 391
    const int spmm_blocks = (NN * 32 + 255) / 256;

    gemm1_mma<<<gblocks, 256, smem12>>>(x, w1, sup, NN);

    // join: spmm needs CSR
    cudaStreamWaitEvent(0, evJoin, 0);

    spmm128_kernel<<<spmm_blocks, 256>>>(sup, off, edge, b1, (uint2*)hh);
    gemm_mma<128, 128><<<gblocks, 256, smem12>>>(hh, w2, sup, NN, NHID);
    spmm128_kernel<<<spmm_blocks, 256>>>(sup, off, edge, b2, (uint2*)hh);
    gemm_mma<64, 128><<<gblocks, 256, smem3>>>(hh, w3, sup3, NN, NCLASS);
    spmm40_ls_kernel<<<spmm_blocks, 256>>>(sup3, off, edge, b3, out);
}